// round 13
// baseline (speedup 1.0000x reference)
#include <cuda_runtime.h>
#include <cuda_bf16.h>
#include <math.h>

#define BB 32
#define TT 2048
#define EE 1024
#define DD 1024
#define AA 1024
#define MROWS 65536  // B*T
#define NITEMS 1024  // 256 smtiles x 4 ntiles
#define NCLUST 74

#if defined(__CUDA_ARCH__) && defined(__CUDA_ARCH_FEAT_SM103_ALL)
#define HAS_TCGEN05 1
#else
#define HAS_TCGEN05 0
#endif

// ---------------------------------------------------------------------------
// W tiles pre-swizzled & quartered:
//   g_w_hi: [2 NTs][16 chunks][4 quarters][16384B]  (quarter = 128 rows x 128B)
//   global a-rows of quarter (NT,q) = [NT*512 + q*128, +128)
// ---------------------------------------------------------------------------
__device__ __nv_bfloat16 g_w_hi[AA * EE];
__device__ __nv_bfloat16 g_w_lo[AA * EE];
__device__ float g_dp[BB * AA];
__device__ float g_energy_part[4 * MROWS];
__device__ float g_ctx_part[16 * BB * EE];

__device__ __forceinline__ unsigned smem_u32(const void* p) {
    unsigned a;
    asm("{ .reg .u64 t; cvta.to.shared.u64 t, %1; cvt.u32.u64 %0, t; }"
        : "=r"(a) : "l"(p));
    return a;
}
#define SWZ(x) ((x) ^ (((x) >> 3) & 0x70))

// ---------------------------------------------------------------------------
__global__ __launch_bounds__(1024) void convert_w_kernel(const float* __restrict__ W)
{
    __shared__ float sh[32][33];
    int tx = threadIdx.x & 31, ty = threadIdx.x >> 5;
    int a0 = blockIdx.x * 32, e0 = blockIdx.y * 32;
    sh[ty][tx] = W[(e0 + ty) * AA + a0 + tx];
    __syncthreads();
    int a = a0 + ty, e = e0 + tx;
    float x = sh[tx][ty];
    __nv_bfloat16 h = __float2bfloat16(x);
    __nv_bfloat16 l = __float2bfloat16(x - __bfloat162float(h));

    int NT = a >> 9;
    int q  = (a >> 7) & 3;
    int rowin = a & 127;
    int chunk = e >> 6, s = (e >> 3) & 7, i = e & 7;
    long long off = ((long long)(NT * 16 + chunk) << 16) + ((long long)q << 14)
                  + SWZ(rowin * 128 + s * 16) + i * 2;
    *reinterpret_cast<__nv_bfloat16*>(reinterpret_cast<char*>(g_w_hi) + off) = h;
    *reinterpret_cast<__nv_bfloat16*>(reinterpret_cast<char*>(g_w_lo) + off) = l;
}

// ---------------------------------------------------------------------------
__global__ __launch_bounds__(256) void dec_proj_kernel(
    const float* __restrict__ dec_out,
    const float* __restrict__ W_dec,
    const float* __restrict__ b_enc)
{
    __shared__ float dsh[DD];
    int b = blockIdx.y;
    int a = blockIdx.x * 256 + threadIdx.x;
    for (int i = threadIdx.x; i < DD; i += 256) dsh[i] = dec_out[b * DD + i];
    __syncthreads();
    float acc = b_enc[a];
#pragma unroll 8
    for (int d = 0; d < DD; d++) acc += dsh[d] * W_dec[d * AA + a];
    g_dp[b * AA + a] = acc;
}

// ---------------------------------------------------------------------------
// PERSISTENT energy kernel — cg2, M=256 x N=256 per item, TMEM D double-
// buffered (cols 0-255 / 256-511), 3-stage 64KB pipeline, 320 threads:
//   warps 0-3  (tid 0-127)  : epilogue
//   warps 4-7  (tid 128-255): A converter
//   tid 256                  : B bulk producer
//   tid 288                  : MMA leader (rank0) / relay (rank1)
// Items: item = cid + 74*j;  ntile = item&3, smtile = item>>2.
// ---------------------------------------------------------------------------
#define ENN 256
#define NCHUNK 16
#define NSTAGE 3
#define STAGE_BYTES 65536
#define OFF_AHI 0
#define OFF_ALO 16384
#define OFF_BHI 32768
#define OFF_BLO 49152
#define SM_STAGE0 1024
#define SM_VS  197632
#define SM_DPS 198656
#define SM_TOTAL 199680
// barriers: bFull[3]@8/16/24, aFull[3]@32/40/48, empty[3]@56/64/72,
//           pready[3]@80/88/96, done[2]@104/112, dfree[2]@120/128

#if HAS_TCGEN05
#define MBARRIER_INIT(addr, cnt) \
    asm volatile("mbarrier.init.shared.b64 [%0], %1;" :: "r"(addr), "r"(cnt) : "memory")
#define MBARRIER_EXPECT_TX(addr, bytes) \
    asm volatile("mbarrier.arrive.expect_tx.shared.b64 _, [%0], %1;" \
                 :: "r"((unsigned)(addr)), "r"((unsigned)(bytes)) : "memory")
#define MBARRIER_ARRIVE(addr) \
    asm volatile("mbarrier.arrive.release.cta.shared::cta.b64 _, [%0];" \
                 :: "r"((unsigned)(addr)) : "memory")
#define MBARRIER_ARRIVE_CLUSTER(local_addr, target_rank) \
    asm volatile( \
        "{\n\t.reg .b32 remAddr32;\n\t" \
        "mapa.shared::cluster.u32 remAddr32, %0, %1;\n\t" \
        "mbarrier.arrive.shared::cluster.b64 _, [remAddr32];\n\t}" \
        :: "r"((unsigned)(local_addr)), "r"((unsigned)(target_rank)) : "memory")

#define MBARRIER_WAIT_PARITY(mbar_smem_addr, phase_parity) do { \
    unsigned _mbar = (unsigned)(mbar_smem_addr); \
    unsigned _parity = (unsigned)(phase_parity); \
    unsigned _done; \
    asm volatile( \
        "{\n\t.reg .pred p;\n\t" \
        "mbarrier.try_wait.parity.acquire.cta.shared::cta.b64 p, [%1], %2;\n\t" \
        "selp.b32 %0, 1, 0, p;\n\t}" \
        : "=r"(_done) : "r"(_mbar), "r"(_parity) : "memory"); \
    if (!_done) { \
        asm volatile( \
            "{\n\t.reg .pred P1;\n\t" \
            "WAIT_LOOP_%=:\n\t" \
            "mbarrier.try_wait.parity.acquire.cta.shared::cta.b64 P1, [%0], %1, 0x989680;\n\t" \
            "@P1 bra.uni WAIT_DONE_%=;\n\t" \
            "bra.uni WAIT_LOOP_%=;\n\t" \
            "WAIT_DONE_%=:\n\t}" \
            :: "r"(_mbar), "r"(_parity) : "memory"); \
    } \
} while (0)

#define TCGEN05_ALLOC_CG2(sm, n) \
    asm volatile("tcgen05.alloc.cta_group::2.sync.aligned.shared::cta.b32 [%0], %1;" \
                 :: "r"((unsigned)(sm)), "r"((unsigned)(n)) : "memory")
#define TCGEN05_RELINQ_CG2() \
    asm volatile("tcgen05.relinquish_alloc_permit.cta_group::2.sync.aligned;")
#define TCGEN05_DEALLOC_CG2(tm, n) \
    asm volatile("tcgen05.dealloc.cta_group::2.sync.aligned.b32 %0, %1;" \
                 :: "r"(tm), "r"((unsigned)(n)))
#define TCGEN05_COMMIT_MC_CG2(mbar, mask) \
    asm volatile("tcgen05.commit.cta_group::2.mbarrier::arrive::one.shared::cluster.multicast::cluster.b64 [%0], %1;" \
                 :: "r"((unsigned)(mbar)), "h"((unsigned short)(mask)) : "memory")
#define TCGEN05_WAIT_LD() asm volatile("tcgen05.wait::ld.sync.aligned;" ::: "memory")
#define TCGEN05_FENCE_BEFORE() asm volatile("tcgen05.fence::before_thread_sync;" ::: "memory")
#define TCGEN05_FENCE_AFTER()  asm volatile("tcgen05.fence::after_thread_sync;" ::: "memory")
#define CLUSTER_SYNC() do { \
    asm volatile("barrier.cluster.arrive.aligned;" ::: "memory"); \
    asm volatile("barrier.cluster.wait.aligned;" ::: "memory"); \
} while (0)
#define FENCE_ASYNC() \
    asm volatile("fence.proxy.async.shared::cta;" ::: "memory")
#define NAMED_BAR_EPI() \
    asm volatile("bar.sync 1, 128;" ::: "memory")

#define TCGEN05_LD_X32(r, tmem_addr) \
    asm volatile( \
        "tcgen05.ld.sync.aligned.32x32b.x32.b32 " \
        "{%0, %1, %2, %3, %4, %5, %6, %7, " \
        " %8, %9, %10, %11, %12, %13, %14, %15, " \
        " %16, %17, %18, %19, %20, %21, %22, %23, " \
        " %24, %25, %26, %27, %28, %29, %30, %31}, [%32];" \
        : "=r"((r)[0]),  "=r"((r)[1]),  "=r"((r)[2]),  "=r"((r)[3]), \
          "=r"((r)[4]),  "=r"((r)[5]),  "=r"((r)[6]),  "=r"((r)[7]), \
          "=r"((r)[8]),  "=r"((r)[9]),  "=r"((r)[10]), "=r"((r)[11]), \
          "=r"((r)[12]), "=r"((r)[13]), "=r"((r)[14]), "=r"((r)[15]), \
          "=r"((r)[16]), "=r"((r)[17]), "=r"((r)[18]), "=r"((r)[19]), \
          "=r"((r)[20]), "=r"((r)[21]), "=r"((r)[22]), "=r"((r)[23]), \
          "=r"((r)[24]), "=r"((r)[25]), "=r"((r)[26]), "=r"((r)[27]), \
          "=r"((r)[28]), "=r"((r)[29]), "=r"((r)[30]), "=r"((r)[31]) \
        : "r"(tmem_addr))

__device__ __forceinline__ void bulk_g2s(unsigned dst, const void* src,
                                         unsigned bytes, unsigned mbar) {
    asm volatile(
        "cp.async.bulk.shared::cluster.global.mbarrier::complete_tx::bytes "
        "[%0], [%1], %2, [%3];"
        :: "r"(dst), "l"(src), "r"(bytes), "r"(mbar) : "memory");
}

static __device__ __forceinline__ unsigned long long make_desc(unsigned addr) {
    const unsigned long long base =
        (2ULL << 61) | (1ULL << 46) | (64ULL << 32) | (1ULL << 16);
    return base | ((unsigned long long)(addr >> 4) & 0x3FFF);
}
__device__ __forceinline__ void mma_bf16_ss_cg2(unsigned d_tmem,
                                                unsigned long long a_desc,
                                                unsigned long long b_desc,
                                                unsigned idesc, unsigned enable) {
    asm volatile(
        "{\n\t.reg .pred p;\n\t"
        "setp.ne.u32 p, %5, 0;\n\t"
        "tcgen05.mma.cta_group::2.kind::f16 [%0], %1, %2, %3, "
        "{%4,%4,%4,%4,%4,%4,%4,%4}, p;\n\t}"
        :: "r"(d_tmem), "l"(a_desc), "l"(b_desc), "r"(idesc), "r"(0u), "r"(enable)
        : "memory");
}
__device__ __forceinline__ float tanh_fast(float x) {
    float y;
    asm("tanh.approx.f32 %0, %1;" : "=f"(y) : "f"(x));
    return y;
}
// dtype=F32, a=BF16, b=BF16, N=256 -> 32<<17, M=256 -> 16<<24
#define EN_IDESC2 0x10400490u
#endif  // HAS_TCGEN05

__global__ __launch_bounds__(320, 1) __cluster_dims__(2, 1, 1)
void energy_kernel(const float* __restrict__ enc,
                   const float* __restrict__ W,     // fallback only
                   const float* __restrict__ v)
{
    extern __shared__ char smem[];
    const int tid = threadIdx.x;

#if HAS_TCGEN05
    const int cid = blockIdx.x >> 1;
    const unsigned sb = smem_u32(smem);
    const int wid = tid >> 5;
    unsigned rank;
    asm("mov.u32 %0, %%cluster_ctarank;" : "=r"(rank));

    if (wid == 0) TCGEN05_ALLOC_CG2(sb, 512);
    if (tid == 0) {
#pragma unroll
        for (int s = 0; s < NSTAGE; s++) {
            MBARRIER_INIT(sb + 8  + s * 8, 1);    // bFull (tx)
            MBARRIER_INIT(sb + 32 + s * 8, 128);  // aFull
            MBARRIER_INIT(sb + 56 + s * 8, 1);    // empty
            MBARRIER_INIT(sb + 80 + s * 8, 1);    // pready
        }
        MBARRIER_INIT(sb + 104, 1);  // done0
        MBARRIER_INIT(sb + 112, 1);  // done1
        MBARRIER_INIT(sb + 120, 2);  // dfree0
        MBARRIER_INIT(sb + 128, 2);  // dfree1
    }
    __syncthreads();
    CLUSTER_SYNC();

    unsigned tmem;
    asm volatile("ld.shared.b32 %0, [%1];" : "=r"(tmem) : "r"(sb));

    const int nItems = (NITEMS - cid + NCLUST - 1) / NCLUST;

    if (tid >= 128 && tid < 256) {
        // ================= A converter (warps 4-7) =================
        const int tid2 = tid - 128;
        int wC[3] = {0, 0, 0};
        float4 ar[16];
        long long cg = 0;

        auto loadA = [&](const float* encAp, int c) {
#pragma unroll
            for (int i = 0; i < 8; i++) {
                int p = tid2 + i * 128;
                int row = p >> 3, k8 = p & 7;
                const float* src = encAp + (long long)row * EE + c * 64 + k8 * 8;
                ar[2 * i]     = *reinterpret_cast<const float4*>(src);
                ar[2 * i + 1] = *reinterpret_cast<const float4*>(src + 4);
            }
        };
        auto stsA = [&](unsigned stage_off) {
            char* base = smem + stage_off;
#pragma unroll
            for (int i = 0; i < 8; i++) {
                int p = tid2 + i * 128;
                int row = p >> 3, k8 = p & 7;
                unsigned d = SWZ((unsigned)(row * 128 + k8 * 16));
                float xs[8] = {ar[2*i].x, ar[2*i].y, ar[2*i].z, ar[2*i].w,
                               ar[2*i+1].x, ar[2*i+1].y, ar[2*i+1].z, ar[2*i+1].w};
                __nv_bfloat16 h[8], l[8];
#pragma unroll
                for (int j = 0; j < 8; j++) {
                    h[j] = __float2bfloat16(xs[j]);
                    l[j] = __float2bfloat16(xs[j] - __bfloat162float(h[j]));
                }
                union { __nv_bfloat162 b2[4]; uint4 q; } ph, pl;
#pragma unroll
                for (int j = 0; j < 4; j++) {
                    ph.b2[j] = __halves2bfloat162(h[2*j], h[2*j+1]);
                    pl.b2[j] = __halves2bfloat162(l[2*j], l[2*j+1]);
                }
                *reinterpret_cast<uint4*>(base + OFF_AHI + d) = ph.q;
                *reinterpret_cast<uint4*>(base + OFF_ALO + d) = pl.q;
            }
        };

        {
            int item0 = cid;
            int mt0 = ((item0 >> 2) << 1) + (int)rank;
            loadA(enc + (long long)mt0 * 128 * EE, 0);
        }
        for (int j = 0; j < nItems; j++) {
            const int item = cid + j * NCLUST;
            const int mtile = ((item >> 2) << 1) + (int)rank;
            const float* encA = enc + (long long)mtile * 128 * EE;
            for (int c = 0; c < NCHUNK; c++) {
                const int s = (int)(cg % 3);
                const int w = wC[s]++;
                if (w > 0) MBARRIER_WAIT_PARITY(sb + 56 + s * 8, (w - 1) & 1);
                stsA(SM_STAGE0 + s * STAGE_BYTES);
                FENCE_ASYNC();
                MBARRIER_ARRIVE(sb + 32 + s * 8);
                cg++;
                if (c + 1 < NCHUNK) {
                    loadA(encA, c + 1);
                } else if (j + 1 < nItems) {
                    const int ni = cid + (j + 1) * NCLUST;
                    const int nmt = ((ni >> 2) << 1) + (int)rank;
                    loadA(enc + (long long)nmt * 128 * EE, 0);
                }
            }
        }
    } else if (tid == 256) {
        // ================= B producer =================
        int bU[3] = {0, 0, 0};
        long long cg = 0;
        for (int j = 0; j < nItems; j++) {
            const int item = cid + j * NCLUST;
            const int ntile = item & 3;
            const int qsel = 2 * ntile + (int)rank;
            const int NT = qsel >> 2, q = qsel & 3;
            const char* wHi = reinterpret_cast<const char*>(g_w_hi)
                            + ((long long)NT * 16 << 16) + ((long long)q << 14);
            const char* wLo = reinterpret_cast<const char*>(g_w_lo)
                            + ((long long)NT * 16 << 16) + ((long long)q << 14);
            for (int c = 0; c < NCHUNK; c++) {
                const int s = (int)(cg % 3);
                const int u2 = bU[s]++;
                if (u2 > 0) MBARRIER_WAIT_PARITY(sb + 56 + s * 8, (u2 - 1) & 1);
                const unsigned tb = sb + SM_STAGE0 + s * STAGE_BYTES;
                const unsigned full = sb + 8 + s * 8;
                MBARRIER_EXPECT_TX(full, 32768);
                bulk_g2s(tb + OFF_BHI, wHi + ((long long)c << 16), 16384, full);
                bulk_g2s(tb + OFF_BLO, wLo + ((long long)c << 16), 16384, full);
                cg++;
            }
        }
    } else if (tid == 288) {
        if (rank == 1) {
            // ================= relay =================
            int bC[3] = {0, 0, 0}, aC[3] = {0, 0, 0};
            long long cg = 0;
            for (int t = 0; t < nItems * NCHUNK; t++) {
                const int s = (int)(cg % 3);
                MBARRIER_WAIT_PARITY(sb + 8  + s * 8, bC[s] & 1); bC[s]++;
                MBARRIER_WAIT_PARITY(sb + 32 + s * 8, aC[s] & 1); aC[s]++;
                MBARRIER_ARRIVE_CLUSTER(sb + 80 + s * 8, 0);
                cg++;
            }
        } else {
            // ================= MMA leader =================
            int bC[3] = {0, 0, 0}, aC[3] = {0, 0, 0}, pC[3] = {0, 0, 0};
            int fC[2] = {0, 0};
            long long cg = 0;
            for (int j = 0; j < nItems; j++) {
                const int d = j & 1;
                if (j >= 2) { MBARRIER_WAIT_PARITY(sb + 120 + d * 8, fC[d] & 1); fC[d]++; }
                for (int c = 0; c < NCHUNK; c++) {
                    const int s = (int)(cg % 3);
                    const unsigned tb = sb + SM_STAGE0 + s * STAGE_BYTES;
                    MBARRIER_WAIT_PARITY(sb + 8  + s * 8, bC[s] & 1); bC[s]++;
                    MBARRIER_WAIT_PARITY(sb + 32 + s * 8, aC[s] & 1); aC[s]++;
                    MBARRIER_WAIT_PARITY(sb + 80 + s * 8, pC[s] & 1); pC[s]++;
                    const unsigned long long dAhi = make_desc(tb + OFF_AHI);
                    const unsigned long long dAlo = make_desc(tb + OFF_ALO);
                    const unsigned long long dBhi = make_desc(tb + OFF_BHI);
                    const unsigned long long dBlo = make_desc(tb + OFF_BLO);
                    const unsigned dt = tmem + d * 256;
#pragma unroll
                    for (int ks = 0; ks < 4; ks++)
                        mma_bf16_ss_cg2(dt, dAhi + ks * 2, dBhi + ks * 2, EN_IDESC2,
                                        (c == 0 && ks == 0) ? 0u : 1u);
#pragma unroll
                    for (int ks = 0; ks < 4; ks++)
                        mma_bf16_ss_cg2(dt, dAhi + ks * 2, dBlo + ks * 2, EN_IDESC2, 1u);
#pragma unroll
                    for (int ks = 0; ks < 4; ks++)
                        mma_bf16_ss_cg2(dt, dAlo + ks * 2, dBhi + ks * 2, EN_IDESC2, 1u);
                    TCGEN05_COMMIT_MC_CG2(sb + 56 + s * 8, 3);
                    cg++;
                }
                TCGEN05_COMMIT_MC_CG2(sb + 104 + d * 8, 3);
            }
        }
    }

    if (tid < 128) {
        // ================= epilogue (warps 0-3) =================
        int dnC[2] = {0, 0};
        float* vs  = reinterpret_cast<float*>(smem + SM_VS);
        float* dps = reinterpret_cast<float*>(smem + SM_DPS);
        for (int j = 0; j < nItems; j++) {
            const int item = cid + j * NCLUST;
            const int ntile = item & 3;
            const int mtile = ((item >> 2) << 1) + (int)rank;
            const long long bt0 = (long long)mtile * 128;
            const int b = mtile >> 4;
            const int nc = ntile * ENN;
            const int d = j & 1;

            vs[tid]        = v[nc + tid];
            vs[tid + 128]  = v[nc + tid + 128];
            dps[tid]       = g_dp[b * AA + nc + tid];
            dps[tid + 128] = g_dp[b * AA + nc + tid + 128];
            NAMED_BAR_EPI();

            MBARRIER_WAIT_PARITY(sb + 104 + d * 8, dnC[d] & 1); dnC[d]++;
            TCGEN05_FENCE_AFTER();
            float rsum = 0.0f;
#pragma unroll 1
            for (int base = 0; base < ENN; base += 64) {
                unsigned d0[32], d1[32];
                TCGEN05_LD_X32(d0, tmem + d * 256 + base);
                TCGEN05_LD_X32(d1, tmem + d * 256 + base + 32);
                TCGEN05_WAIT_LD();
#pragma unroll
                for (int jj = 0; jj < 32; jj++) {
                    float x = __uint_as_float(d0[jj]) + dps[base + jj];
                    rsum += vs[base + jj] * tanh_fast(x);
                }
#pragma unroll
                for (int jj = 0; jj < 32; jj++) {
                    float x = __uint_as_float(d1[jj]) + dps[base + 32 + jj];
                    rsum += vs[base + 32 + jj] * tanh_fast(x);
                }
            }
            g_energy_part[(long long)ntile * MROWS + bt0 + tid] = rsum;
            TCGEN05_FENCE_BEFORE();
            NAMED_BAR_EPI();
            if (tid == 0) MBARRIER_ARRIVE_CLUSTER(sb + 120 + d * 8, 0);
        }
    }

    __syncthreads();
    if (wid == 0) {
        TCGEN05_RELINQ_CG2();
        TCGEN05_DEALLOC_CG2(tmem, 512);
    }
    CLUSTER_SYNC();

#else
    // =================== FFMA fallback (persistent, 256 active threads) =====
    #define TK 32
    #define XS_STRIDE 132
    #define WS_STRIDE 68
    if (tid < 256) {
        float* x_s = reinterpret_cast<float*>(smem);
        float* w_s = reinterpret_cast<float*>(smem) + TK * XS_STRIDE;
        const int ty = tid >> 4;
        const int tx = tid & 15;

        for (int wk = blockIdx.x; wk < 2048; wk += 2 * NCLUST) {
            const int mtile = wk >> 2;
            const int ntile = wk & 3;
            const long long bt0 = (long long)mtile * 128;
            const int b = mtile >> 4;
            const int nc = ntile * 256;
            const float* __restrict__ dp = g_dp + b * AA;

            float rowsum[8];
#pragma unroll
            for (int i = 0; i < 8; i++) rowsum[i] = 0.0f;

            for (int ncc = nc; ncc < nc + 256; ncc += 64) {
                float acc[8][4];
#pragma unroll
                for (int i = 0; i < 8; i++)
#pragma unroll
                    for (int jj = 0; jj < 4; jj++) acc[i][jj] = 0.0f;

                for (int k0 = 0; k0 < EE; k0 += TK) {
#pragma unroll
                    for (int i = 0; i < 4; i++) {
                        int f4  = tid + i * 256;
                        int row = f4 >> 3;
                        int kc  = (f4 & 7) << 2;
                        float4 xv = *reinterpret_cast<const float4*>(
                            &enc[(long long)(bt0 + row) * EE + k0 + kc]);
                        x_s[(kc + 0) * XS_STRIDE + row] = xv.x;
                        x_s[(kc + 1) * XS_STRIDE + row] = xv.y;
                        x_s[(kc + 2) * XS_STRIDE + row] = xv.z;
                        x_s[(kc + 3) * XS_STRIDE + row] = xv.w;
                    }
#pragma unroll
                    for (int i = 0; i < 2; i++) {
                        int f4 = tid + i * 256;
                        int kk = f4 >> 4;
                        int cc = (f4 & 15) << 2;
                        float4 wv = *reinterpret_cast<const float4*>(
                            &W[(long long)(k0 + kk) * AA + ncc + cc]);
                        *reinterpret_cast<float4*>(&w_s[kk * WS_STRIDE + cc]) = wv;
                    }
                    __syncthreads();
#pragma unroll
                    for (int kk = 0; kk < TK; kk++) {
                        float4 xa = *reinterpret_cast<const float4*>(&x_s[kk * XS_STRIDE + ty * 8]);
                        float4 xb = *reinterpret_cast<const float4*>(&x_s[kk * XS_STRIDE + ty * 8 + 4]);
                        float4 wv = *reinterpret_cast<const float4*>(&w_s[kk * WS_STRIDE + tx * 4]);
                        float xr[8] = {xa.x, xa.y, xa.z, xa.w, xb.x, xb.y, xb.z, xb.w};
                        float wr[4] = {wv.x, wv.y, wv.z, wv.w};
#pragma unroll
                        for (int i = 0; i < 8; i++)
#pragma unroll
                            for (int jj = 0; jj < 4; jj++)
                                acc[i][jj] += xr[i] * wr[jj];
                    }
                    __syncthreads();
                }
#pragma unroll
                for (int jj = 0; jj < 4; jj++) {
                    int col = ncc + tx * 4 + jj;
                    float vj  = v[col];
                    float dpv = dp[col];
#pragma unroll
                    for (int i = 0; i < 8; i++)
                        rowsum[i] += vj * tanhf(acc[i][jj] + dpv);
                }
            }
#pragma unroll
            for (int off = 8; off > 0; off >>= 1)
#pragma unroll
                for (int i = 0; i < 8; i++)
                    rowsum[i] += __shfl_down_sync(0xffffffffu, rowsum[i], off, 16);
            if (tx == 0) {
#pragma unroll
                for (int i = 0; i < 8; i++)
                    g_energy_part[(long long)ntile * MROWS + bt0 + ty * 8 + i] = rowsum[i];
            }
            __syncthreads();
        }
    }
    #undef TK
    #undef XS_STRIDE
    #undef WS_STRIDE
#endif
}

// ---------------------------------------------------------------------------
// sum 4 energy partials, mask, softmax -> att
// ---------------------------------------------------------------------------
__global__ __launch_bounds__(256) void softmax_kernel(
    const int* __restrict__ x_lens,
    float* __restrict__ att)
{
    __shared__ float red[32];
    const int b = blockIdx.x;
    const int tid = threadIdx.x;
    const int len = x_lens[b];
    float* e = att + b * TT;

    float vals[8];
    float mx = -INFINITY;
#pragma unroll
    for (int i = 0; i < 8; i++) {
        int t = i * 256 + tid;
        int idx = b * TT + t;
        float val = g_energy_part[idx] + g_energy_part[MROWS + idx]
                  + g_energy_part[2 * MROWS + idx] + g_energy_part[3 * MROWS + idx];
        val = val * (t < len ? 1.0f : 0.0f);
        vals[i] = val;
        mx = fmaxf(mx, val);
    }
    for (int off = 16; off > 0; off >>= 1)
        mx = fmaxf(mx, __shfl_down_sync(0xffffffffu, mx, off));
    if ((tid & 31) == 0) red[tid >> 5] = mx;
    __syncthreads();
    if (tid < 32) {
        float m = (tid < 8) ? red[tid] : -INFINITY;
        for (int off = 4; off > 0; off >>= 1)
            m = fmaxf(m, __shfl_down_sync(0xffffffffu, m, off));
        if (tid == 0) red[0] = m;
    }
    __syncthreads();
    mx = red[0];

    float sum = 0.0f;
#pragma unroll
    for (int i = 0; i < 8; i++) {
        vals[i] = expf(vals[i] - mx);
        sum += vals[i];
    }
    for (int off = 16; off > 0; off >>= 1)
        sum += __shfl_down_sync(0xffffffffu, sum, off);
    __syncthreads();
    if ((tid & 31) == 0) red[tid >> 5] = sum;
    __syncthreads();
    if (tid < 32) {
        float s = (tid < 8) ? red[tid] : 0.0f;
        for (int off = 4; off > 0; off >>= 1)
            s += __shfl_down_sync(0xffffffffu, s, off);
        if (tid == 0) red[0] = s;
    }
    __syncthreads();
    float inv = 1.0f / red[0];

#pragma unroll
    for (int i = 0; i < 8; i++) {
        int t = i * 256 + tid;
        e[t] = vals[i] * inv;
    }
}

// ---------------------------------------------------------------------------
// context partials: 16 T-chunks of 128, float4 per thread, then reduce
// ---------------------------------------------------------------------------
__global__ __launch_bounds__(256) void context_part_kernel(
    const float* __restrict__ enc,
    const float* __restrict__ att)
{
    __shared__ float a_s[128];
    const int b = blockIdx.y;
    const int t0 = blockIdx.x * 128;
    if (threadIdx.x < 128) a_s[threadIdx.x] = att[b * TT + t0 + threadIdx.x];
    __syncthreads();
    const float4* __restrict__ base =
        reinterpret_cast<const float4*>(enc + ((long long)b * TT + t0) * EE)
        + threadIdx.x;
    float4 acc = make_float4(0.f, 0.f, 0.f, 0.f);
#pragma unroll 4
    for (int t = 0; t < 128; t++) {
        float4 x = base[(long long)t * 256];
        float a = a_s[t];
        acc.x += x.x * a; acc.y += x.y * a; acc.z += x.z * a; acc.w += x.w * a;
    }
    reinterpret_cast<float4*>(
        g_ctx_part + ((long long)blockIdx.x * BB + b) * EE)[threadIdx.x] = acc;
}

__global__ __launch_bounds__(256) void context_reduce_kernel(float* __restrict__ ctx)
{
    int i = blockIdx.x * 256 + threadIdx.x;
    float acc = 0.0f;
#pragma unroll
    for (int p = 0; p < 16; p++) acc += g_ctx_part[(long long)p * (BB * EE) + i];
    ctx[i] = acc;
}

// ---------------------------------------------------------------------------
extern "C" void kernel_launch(void* const* d_in, const int* in_sizes, int n_in,
                              void* d_out, int out_size)
{
    const float* enc_out = (const float*)d_in[0];   // [B,T,E]
    const int*   x_lens  = (const int*)  d_in[1];   // [B]
    const float* dec_out = (const float*)d_in[2];   // [B,1,D]
    const float* W_enc   = (const float*)d_in[4];   // [E,A]
    const float* b_enc   = (const float*)d_in[5];   // [A]
    const float* W_dec   = (const float*)d_in[6];   // [D,A]
    const float* v       = (const float*)d_in[7];   // [A]

    float* out = (float*)d_out;
    float* ctx = out;               // [B, E]
    float* att = out + BB * EE;     // [B, T]

    cudaFuncSetAttribute(energy_kernel,
                         cudaFuncAttributeMaxDynamicSharedMemorySize, SM_TOTAL);

    convert_w_kernel<<<dim3(32, 32), 1024>>>(W_enc);
    dec_proj_kernel<<<dim3(AA / 256, BB), 256>>>(dec_out, W_dec, b_enc);
    energy_kernel<<<2 * NCLUST, 320, SM_TOTAL>>>(enc_out, W_enc, v);
    softmax_kernel<<<BB, 256>>>(x_lens, att);
    context_part_kernel<<<dim3(16, BB), 256>>>(enc_out, att);
    context_reduce_kernel<<<(BB * EE) / 256, 256>>>(ctx);
}

// round 14
// speedup vs baseline: 1.3943x; 1.3943x over previous
#include <cuda_runtime.h>
#include <cuda_bf16.h>
#include <math.h>

#define BB 32
#define TT 2048
#define EE 1024
#define DD 1024
#define AA 1024
#define MROWS 65536  // B*T

#if defined(__CUDA_ARCH__) && defined(__CUDA_ARCH_FEAT_SM103_ALL)
#define HAS_TCGEN05 1
#else
#define HAS_TCGEN05 0
#endif

// ---------------------------------------------------------------------------
// Device scratch.  W tiles pre-swizzled & quartered:
//   g_w_hi: [2 NTs][16 chunks][4 quarters][16384B]  (quarter = 128 rows x 128B)
// ---------------------------------------------------------------------------
__device__ __nv_bfloat16 g_w_hi[AA * EE];
__device__ __nv_bfloat16 g_w_lo[AA * EE];
__device__ float g_dp_part[4 * BB * AA];     // 4 K-chunk partials of dec_proj
__device__ float g_energy_part[2 * MROWS];
__device__ float g_ctx_part[16 * BB * EE];

__device__ __forceinline__ unsigned smem_u32(const void* p) {
    unsigned a;
    asm("{ .reg .u64 t; cvta.to.shared.u64 t, %1; cvt.u32.u64 %0, t; }"
        : "=r"(a) : "l"(p));
    return a;
}
#define SWZ(x) ((x) ^ (((x) >> 3) & 0x70))

// ---------------------------------------------------------------------------
// W_enc [E,A] -> transposed bf16 hi/lo, quartered tile layout.
// ---------------------------------------------------------------------------
__global__ __launch_bounds__(1024) void convert_w_kernel(const float* __restrict__ W)
{
    __shared__ float sh[32][33];
    int tx = threadIdx.x & 31, ty = threadIdx.x >> 5;
    int a0 = blockIdx.x * 32, e0 = blockIdx.y * 32;
    sh[ty][tx] = W[(e0 + ty) * AA + a0 + tx];
    __syncthreads();
    int a = a0 + ty, e = e0 + tx;
    float x = sh[tx][ty];
    __nv_bfloat16 h = __float2bfloat16(x);
    __nv_bfloat16 l = __float2bfloat16(x - __bfloat162float(h));

    int NT = a >> 9;
    int q  = (a >> 7) & 3;
    int rowin = a & 127;
    int chunk = e >> 6, s = (e >> 3) & 7, i = e & 7;
    long long off = ((long long)(NT * 16 + chunk) << 16) + ((long long)q << 14)
                  + SWZ(rowin * 128 + s * 16) + i * 2;
    *reinterpret_cast<__nv_bfloat16*>(reinterpret_cast<char*>(g_w_hi) + off) = h;
    *reinterpret_cast<__nv_bfloat16*>(reinterpret_cast<char*>(g_w_lo) + off) = l;
}

// ---------------------------------------------------------------------------
// dec_proj partials: g_dp_part[kc][b][a] = (kc==0 ? b_enc[a] : 0)
//                    + sum_{d in kc-chunk} dec_out[b,d] * W_dec[d,a]
// grid (4, 32, 4): (a-block, batch, k-chunk).  256-iteration loops.
// ---------------------------------------------------------------------------
__global__ __launch_bounds__(256) void dec_proj_kernel(
    const float* __restrict__ dec_out,
    const float* __restrict__ W_dec,
    const float* __restrict__ b_enc)
{
    __shared__ float dsh[256];
    const int b  = blockIdx.y;
    const int kc = blockIdx.z;
    const int a  = blockIdx.x * 256 + threadIdx.x;
    dsh[threadIdx.x] = dec_out[b * DD + kc * 256 + threadIdx.x];
    __syncthreads();
    float acc = (kc == 0) ? b_enc[a] : 0.0f;
    const float* __restrict__ Wp = W_dec + (long long)(kc * 256) * AA + a;
#pragma unroll 8
    for (int d = 0; d < 256; d++) acc += dsh[d] * Wp[(long long)d * AA];
    g_dp_part[((kc * BB) + b) * AA + a] = acc;
}

// ---------------------------------------------------------------------------
// Energy kernel — cta_group::2, M=256 x N=512 per pair, 2-stage pipeline,
// warp-specialized (R12 proven structure) + 256-thread split epilogue.
// Grid 1024, cluster 2.  pair = u>>1: ntile = pair&1, smtile = pair>>1.
// ---------------------------------------------------------------------------
#define ENN 512
#define NCHUNK 16
#define NSTAGE 2
#define STAGE_BYTES 98304
#define OFF_AHI 0
#define OFF_ALO 16384
#define OFF_BHI 32768
#define OFF_BLO 65536
#define SM_STAGE0 1024
#define SM_VS 197632
#define SM_DPS 199680
#define SM_TOTAL 201728

#if HAS_TCGEN05
#define MBARRIER_INIT(addr, cnt) \
    asm volatile("mbarrier.init.shared.b64 [%0], %1;" :: "r"(addr), "r"(cnt) : "memory")
#define MBARRIER_EXPECT_TX(addr, bytes) \
    asm volatile("mbarrier.arrive.expect_tx.shared.b64 _, [%0], %1;" \
                 :: "r"((unsigned)(addr)), "r"((unsigned)(bytes)) : "memory")
#define MBARRIER_ARRIVE(addr) \
    asm volatile("mbarrier.arrive.release.cta.shared::cta.b64 _, [%0];" \
                 :: "r"((unsigned)(addr)) : "memory")
#define MBARRIER_ARRIVE_CLUSTER(local_addr, target_rank) \
    asm volatile( \
        "{\n\t.reg .b32 remAddr32;\n\t" \
        "mapa.shared::cluster.u32 remAddr32, %0, %1;\n\t" \
        "mbarrier.arrive.shared::cluster.b64 _, [remAddr32];\n\t}" \
        :: "r"((unsigned)(local_addr)), "r"((unsigned)(target_rank)) : "memory")

#define MBARRIER_WAIT_PARITY(mbar_smem_addr, phase_parity) do { \
    unsigned _mbar = (unsigned)(mbar_smem_addr); \
    unsigned _parity = (unsigned)(phase_parity); \
    unsigned _done; \
    asm volatile( \
        "{\n\t.reg .pred p;\n\t" \
        "mbarrier.try_wait.parity.acquire.cta.shared::cta.b64 p, [%1], %2;\n\t" \
        "selp.b32 %0, 1, 0, p;\n\t}" \
        : "=r"(_done) : "r"(_mbar), "r"(_parity) : "memory"); \
    if (!_done) { \
        asm volatile( \
            "{\n\t.reg .pred P1;\n\t" \
            "WAIT_LOOP_%=:\n\t" \
            "mbarrier.try_wait.parity.acquire.cta.shared::cta.b64 P1, [%0], %1, 0x989680;\n\t" \
            "@P1 bra.uni WAIT_DONE_%=;\n\t" \
            "bra.uni WAIT_LOOP_%=;\n\t" \
            "WAIT_DONE_%=:\n\t}" \
            :: "r"(_mbar), "r"(_parity) : "memory"); \
    } \
} while (0)

#define TCGEN05_ALLOC_CG2(sm, n) \
    asm volatile("tcgen05.alloc.cta_group::2.sync.aligned.shared::cta.b32 [%0], %1;" \
                 :: "r"((unsigned)(sm)), "r"((unsigned)(n)) : "memory")
#define TCGEN05_RELINQ_CG2() \
    asm volatile("tcgen05.relinquish_alloc_permit.cta_group::2.sync.aligned;")
#define TCGEN05_DEALLOC_CG2(tm, n) \
    asm volatile("tcgen05.dealloc.cta_group::2.sync.aligned.b32 %0, %1;" \
                 :: "r"(tm), "r"((unsigned)(n)))
#define TCGEN05_COMMIT_MC_CG2(mbar, mask) \
    asm volatile("tcgen05.commit.cta_group::2.mbarrier::arrive::one.shared::cluster.multicast::cluster.b64 [%0], %1;" \
                 :: "r"((unsigned)(mbar)), "h"((unsigned short)(mask)) : "memory")
#define TCGEN05_WAIT_LD() asm volatile("tcgen05.wait::ld.sync.aligned;" ::: "memory")
#define TCGEN05_FENCE_BEFORE() asm volatile("tcgen05.fence::before_thread_sync;" ::: "memory")
#define TCGEN05_FENCE_AFTER()  asm volatile("tcgen05.fence::after_thread_sync;" ::: "memory")
#define CLUSTER_SYNC() do { \
    asm volatile("barrier.cluster.arrive.aligned;" ::: "memory"); \
    asm volatile("barrier.cluster.wait.aligned;" ::: "memory"); \
} while (0)
#define FENCE_ASYNC() \
    asm volatile("fence.proxy.async.shared::cta;" ::: "memory")

#define TCGEN05_LD_X32(r, tmem_addr) \
    asm volatile( \
        "tcgen05.ld.sync.aligned.32x32b.x32.b32 " \
        "{%0, %1, %2, %3, %4, %5, %6, %7, " \
        " %8, %9, %10, %11, %12, %13, %14, %15, " \
        " %16, %17, %18, %19, %20, %21, %22, %23, " \
        " %24, %25, %26, %27, %28, %29, %30, %31}, [%32];" \
        : "=r"((r)[0]),  "=r"((r)[1]),  "=r"((r)[2]),  "=r"((r)[3]), \
          "=r"((r)[4]),  "=r"((r)[5]),  "=r"((r)[6]),  "=r"((r)[7]), \
          "=r"((r)[8]),  "=r"((r)[9]),  "=r"((r)[10]), "=r"((r)[11]), \
          "=r"((r)[12]), "=r"((r)[13]), "=r"((r)[14]), "=r"((r)[15]), \
          "=r"((r)[16]), "=r"((r)[17]), "=r"((r)[18]), "=r"((r)[19]), \
          "=r"((r)[20]), "=r"((r)[21]), "=r"((r)[22]), "=r"((r)[23]), \
          "=r"((r)[24]), "=r"((r)[25]), "=r"((r)[26]), "=r"((r)[27]), \
          "=r"((r)[28]), "=r"((r)[29]), "=r"((r)[30]), "=r"((r)[31]) \
        : "r"(tmem_addr))

__device__ __forceinline__ void bulk_g2s(unsigned dst, const void* src,
                                         unsigned bytes, unsigned mbar) {
    asm volatile(
        "cp.async.bulk.shared::cluster.global.mbarrier::complete_tx::bytes "
        "[%0], [%1], %2, [%3];"
        :: "r"(dst), "l"(src), "r"(bytes), "r"(mbar) : "memory");
}

static __device__ __forceinline__ unsigned long long make_desc(unsigned addr) {
    const unsigned long long base =
        (2ULL << 61) | (1ULL << 46) | (64ULL << 32) | (1ULL << 16);
    return base | ((unsigned long long)(addr >> 4) & 0x3FFF);
}
__device__ __forceinline__ void mma_bf16_ss_cg2(unsigned d_tmem,
                                                unsigned long long a_desc,
                                                unsigned long long b_desc,
                                                unsigned idesc, unsigned enable) {
    asm volatile(
        "{\n\t.reg .pred p;\n\t"
        "setp.ne.u32 p, %5, 0;\n\t"
        "tcgen05.mma.cta_group::2.kind::f16 [%0], %1, %2, %3, "
        "{%4,%4,%4,%4,%4,%4,%4,%4}, p;\n\t}"
        :: "r"(d_tmem), "l"(a_desc), "l"(b_desc), "r"(idesc), "r"(0u), "r"(enable)
        : "memory");
}
__device__ __forceinline__ float tanh_fast(float x) {
    float y;
    asm("tanh.approx.f32 %0, %1;" : "=f"(y) : "f"(x));
    return y;
}
// dtype=F32(1<<4), a=BF16(1<<7), b=BF16(1<<10), N=256 -> 32<<17, M=256 -> 16<<24
#define EN_IDESC2 0x10400490u
#endif  // HAS_TCGEN05

__global__ __launch_bounds__(256, 1) __cluster_dims__(2, 1, 1)
void energy_kernel(const float* __restrict__ enc,   // fp32 [B*T, E]
                   const float* __restrict__ W,     // fp32 (fallback only)
                   const float* __restrict__ v)
{
    extern __shared__ char smem[];
    const int tid = threadIdx.x;
    const unsigned u = blockIdx.x;
    const unsigned pair = u >> 1;
    const int ntile = pair & 1;
    const int smtile = pair >> 1;
    const int rank_s = u & 1;
    const int mtile = smtile * 2 + rank_s;
    const long long bt0 = (long long)mtile * 128;
    const int b = mtile >> 4;
    const int nc = ntile * ENN;

#if HAS_TCGEN05
    const unsigned sb = smem_u32(smem);
    const int wid = tid >> 5;
    unsigned rank;
    asm("mov.u32 %0, %%cluster_ctarank;" : "=r"(rank));

    if (wid == 0) TCGEN05_ALLOC_CG2(sb, 512);
    if (tid == 0) {
#pragma unroll
        for (int s = 0; s < NSTAGE; s++) {
            MBARRIER_INIT(sb + 8  + s * 8, 1);    // bFull (tx)
            MBARRIER_INIT(sb + 24 + s * 8, 128);  // aFull
            MBARRIER_INIT(sb + 40 + s * 8, 1);    // empty (commit)
            MBARRIER_INIT(sb + 56 + s * 8, 1);    // pready
        }
        MBARRIER_INIT(sb + 72, 1);                // done
    }
    __syncthreads();
    CLUSTER_SYNC();

    unsigned tmem;
    asm volatile("ld.shared.b32 %0, [%1];" : "=r"(tmem) : "r"(sb));

    {
        float* vs  = reinterpret_cast<float*>(smem + SM_VS);
        float* dps = reinterpret_cast<float*>(smem + SM_DPS);
        vs[tid]        = v[nc + tid];
        vs[tid + 256]  = v[nc + tid + 256];
        const int base0 = b * AA + nc;
        dps[tid] = g_dp_part[base0 + tid]
                 + g_dp_part[BB * AA + base0 + tid]
                 + g_dp_part[2 * BB * AA + base0 + tid]
                 + g_dp_part[3 * BB * AA + base0 + tid];
        dps[tid + 256] = g_dp_part[base0 + tid + 256]
                       + g_dp_part[BB * AA + base0 + tid + 256]
                       + g_dp_part[2 * BB * AA + base0 + tid + 256]
                       + g_dp_part[3 * BB * AA + base0 + tid + 256];
    }

    const char* wHi = reinterpret_cast<const char*>(g_w_hi)
                    + ((long long)ntile * 16 << 16);
    const char* wLo = reinterpret_cast<const char*>(g_w_lo)
                    + ((long long)ntile * 16 << 16);
    const long long qa = (long long)rank * 16384;
    const long long qb = (long long)(2 + rank) * 16384;

    if (tid >= 128) {
        // ---------------- A converter (warps 4-7) ----------------
        const float* __restrict__ encA = enc + bt0 * EE;
        const int tid2 = tid - 128;
        float4 ar[16];

        auto loadA = [&](int c) {
#pragma unroll
            for (int i = 0; i < 8; i++) {
                int p = tid2 + i * 128;
                int row = p >> 3, k8 = p & 7;
                const float* src = encA + (long long)row * EE + c * 64 + k8 * 8;
                ar[2 * i]     = *reinterpret_cast<const float4*>(src);
                ar[2 * i + 1] = *reinterpret_cast<const float4*>(src + 4);
            }
        };
        auto stsA = [&](unsigned stage_off) {
            char* base = smem + stage_off;
#pragma unroll
            for (int i = 0; i < 8; i++) {
                int p = tid2 + i * 128;
                int row = p >> 3, k8 = p & 7;
                unsigned d = SWZ((unsigned)(row * 128 + k8 * 16));
                float xs[8] = {ar[2*i].x, ar[2*i].y, ar[2*i].z, ar[2*i].w,
                               ar[2*i+1].x, ar[2*i+1].y, ar[2*i+1].z, ar[2*i+1].w};
                __nv_bfloat16 h[8], l[8];
#pragma unroll
                for (int j = 0; j < 8; j++) {
                    h[j] = __float2bfloat16(xs[j]);
                    l[j] = __float2bfloat16(xs[j] - __bfloat162float(h[j]));
                }
                union { __nv_bfloat162 b2[4]; uint4 q; } ph, pl;
#pragma unroll
                for (int j = 0; j < 4; j++) {
                    ph.b2[j] = __halves2bfloat162(h[2*j], h[2*j+1]);
                    pl.b2[j] = __halves2bfloat162(l[2*j], l[2*j+1]);
                }
                *reinterpret_cast<uint4*>(base + OFF_AHI + d) = ph.q;
                *reinterpret_cast<uint4*>(base + OFF_ALO + d) = pl.q;
            }
        };

        loadA(0);
        for (int c = 0; c < NCHUNK; c++) {
            const int s = c & 1;
            if (c >= NSTAGE)
                MBARRIER_WAIT_PARITY(sb + 40 + s * 8, ((c - NSTAGE) >> 1) & 1);
            stsA(SM_STAGE0 + s * STAGE_BYTES);
            FENCE_ASYNC();
            MBARRIER_ARRIVE(sb + 24 + s * 8);
            if (c + 1 < NCHUNK) loadA(c + 1);
        }
    } else if (tid == 0) {
        // ---------------- B producer ----------------
        for (int c = 0; c < NCHUNK; c++) {
            const int s = c & 1;
            const unsigned tb = sb + SM_STAGE0 + s * STAGE_BYTES;
            const unsigned full = sb + 8 + s * 8;
            if (c >= NSTAGE)
                MBARRIER_WAIT_PARITY(sb + 40 + s * 8, ((c - NSTAGE) >> 1) & 1);
            MBARRIER_EXPECT_TX(full, 65536);
            const long long cw = (long long)c << 16;
            bulk_g2s(tb + OFF_BHI,          wHi + cw + qa, 16384, full);
            bulk_g2s(tb + OFF_BHI + 16384,  wHi + cw + qb, 16384, full);
            bulk_g2s(tb + OFF_BLO,          wLo + cw + qa, 16384, full);
            bulk_g2s(tb + OFF_BLO + 16384,  wLo + cw + qb, 16384, full);
        }
    } else if (tid == 32) {
        if (rank == 1) {
            // relay: local (aFull & bFull) -> leader's pready
            for (int c = 0; c < NCHUNK; c++) {
                const int s = c & 1;
                const int par = (c >> 1) & 1;
                MBARRIER_WAIT_PARITY(sb + 8  + s * 8, par);
                MBARRIER_WAIT_PARITY(sb + 24 + s * 8, par);
                MBARRIER_ARRIVE_CLUSTER(sb + 56 + s * 8, 0);
            }
        } else {
            // ---------------- MMA leader ----------------
            for (int c = 0; c < NCHUNK; c++) {
                const int s = c & 1;
                const unsigned tb = sb + SM_STAGE0 + s * STAGE_BYTES;
                const int par = (c >> 1) & 1;
                MBARRIER_WAIT_PARITY(sb + 8  + s * 8, par);
                MBARRIER_WAIT_PARITY(sb + 24 + s * 8, par);
                MBARRIER_WAIT_PARITY(sb + 56 + s * 8, par);
                const unsigned long long dAhi = make_desc(tb + OFF_AHI);
                const unsigned long long dAlo = make_desc(tb + OFF_ALO);
                const unsigned long long dB[2][2] = {
                    { make_desc(tb + OFF_BHI), make_desc(tb + OFF_BHI + 16384) },
                    { make_desc(tb + OFF_BLO), make_desc(tb + OFF_BLO + 16384) } };
#pragma unroll
                for (int ks = 0; ks < 4; ks++)
#pragma unroll
                    for (int nh = 0; nh < 2; nh++)
                        mma_bf16_ss_cg2(tmem + nh * 256, dAhi + ks * 2,
                                        dB[0][nh] + ks * 2, EN_IDESC2,
                                        (c == 0 && ks == 0) ? 0u : 1u);
#pragma unroll
                for (int ks = 0; ks < 4; ks++)
#pragma unroll
                    for (int nh = 0; nh < 2; nh++)
                        mma_bf16_ss_cg2(tmem + nh * 256, dAhi + ks * 2,
                                        dB[1][nh] + ks * 2, EN_IDESC2, 1u);
#pragma unroll
                for (int ks = 0; ks < 4; ks++)
#pragma unroll
                    for (int nh = 0; nh < 2; nh++)
                        mma_bf16_ss_cg2(tmem + nh * 256, dAlo + ks * 2,
                                        dB[0][nh] + ks * 2, EN_IDESC2, 1u);
                TCGEN05_COMMIT_MC_CG2(sb + 40 + s * 8, 3);
            }
            TCGEN05_COMMIT_MC_CG2(sb + 72, 3);
        }
    }

    // ---------------- split epilogue: all 256 threads ----------------
    MBARRIER_WAIT_PARITY(sb + 72, 0);
    TCGEN05_FENCE_AFTER();
    {
        const float* __restrict__ vs  = reinterpret_cast<const float*>(smem + SM_VS);
        const float* __restrict__ dps = reinterpret_cast<const float*>(smem + SM_DPS);
        float* part = reinterpret_cast<float*>(smem + SM_STAGE0);  // stages idle now
        const int colbase = (tid >> 7) * 256;   // warps 0-3 -> 0, warps 4-7 -> 256
        float rsum = 0.0f;
#pragma unroll 1
        for (int base = 0; base < 256; base += 64) {
            unsigned d0[32], d1[32];
            TCGEN05_LD_X32(d0, tmem + colbase + base);
            TCGEN05_LD_X32(d1, tmem + colbase + base + 32);
            TCGEN05_WAIT_LD();
#pragma unroll
            for (int j = 0; j < 32; j++) {
                float x = __uint_as_float(d0[j]) + dps[colbase + base + j];
                rsum += vs[colbase + base + j] * tanh_fast(x);
            }
#pragma unroll
            for (int j = 0; j < 32; j++) {
                float x = __uint_as_float(d1[j]) + dps[colbase + base + 32 + j];
                rsum += vs[colbase + base + 32 + j] * tanh_fast(x);
            }
        }
        part[tid] = rsum;
        TCGEN05_FENCE_BEFORE();
        __syncthreads();
        if (tid < 128)
            g_energy_part[(long long)ntile * MROWS + bt0 + tid] =
                part[tid] + part[tid + 128];
    }
    __syncthreads();
    if (wid == 0) {
        TCGEN05_RELINQ_CG2();
        TCGEN05_DEALLOC_CG2(tmem, 512);
    }
    CLUSTER_SYNC();

#else
    // =================== FFMA fallback path ===================
    #define TK 32
    #define XS_STRIDE 132
    #define WS_STRIDE 68
    float* x_s = reinterpret_cast<float*>(smem);
    float* w_s = reinterpret_cast<float*>(smem) + TK * XS_STRIDE;

    const int ty = tid >> 4;
    const int tx = tid & 15;

    float rowsum[8];
#pragma unroll
    for (int i = 0; i < 8; i++) rowsum[i] = 0.0f;

    for (int ncc = nc; ncc < nc + ENN; ncc += 64) {
        float acc[8][4];
#pragma unroll
        for (int i = 0; i < 8; i++)
#pragma unroll
            for (int j = 0; j < 4; j++) acc[i][j] = 0.0f;

        for (int k0 = 0; k0 < EE; k0 += TK) {
#pragma unroll
            for (int i = 0; i < 4; i++) {
                int f4  = tid + i * 256;
                int row = f4 >> 3;
                int kc  = (f4 & 7) << 2;
                float4 xv = *reinterpret_cast<const float4*>(
                    &enc[(long long)(bt0 + row) * EE + k0 + kc]);
                x_s[(kc + 0) * XS_STRIDE + row] = xv.x;
                x_s[(kc + 1) * XS_STRIDE + row] = xv.y;
                x_s[(kc + 2) * XS_STRIDE + row] = xv.z;
                x_s[(kc + 3) * XS_STRIDE + row] = xv.w;
            }
#pragma unroll
            for (int i = 0; i < 2; i++) {
                int f4 = tid + i * 256;
                int kk = f4 >> 4;
                int cc = (f4 & 15) << 2;
                float4 wv = *reinterpret_cast<const float4*>(
                    &W[(long long)(k0 + kk) * AA + ncc + cc]);
                *reinterpret_cast<float4*>(&w_s[kk * WS_STRIDE + cc]) = wv;
            }
            __syncthreads();

#pragma unroll
            for (int kk = 0; kk < TK; kk++) {
                float4 xa = *reinterpret_cast<const float4*>(&x_s[kk * XS_STRIDE + ty * 8]);
                float4 xb = *reinterpret_cast<const float4*>(&x_s[kk * XS_STRIDE + ty * 8 + 4]);
                float4 wv = *reinterpret_cast<const float4*>(&w_s[kk * WS_STRIDE + tx * 4]);
                float xr[8] = {xa.x, xa.y, xa.z, xa.w, xb.x, xb.y, xb.z, xb.w};
                float wr[4] = {wv.x, wv.y, wv.z, wv.w};
#pragma unroll
                for (int i = 0; i < 8; i++)
#pragma unroll
                    for (int j = 0; j < 4; j++)
                        acc[i][j] += xr[i] * wr[j];
            }
            __syncthreads();
        }

#pragma unroll
        for (int j = 0; j < 4; j++) {
            int col = ncc + tx * 4 + j;
            float vj  = v[col];
            float dpv = g_dp_part[b * AA + col]
                      + g_dp_part[BB * AA + b * AA + col]
                      + g_dp_part[2 * BB * AA + b * AA + col]
                      + g_dp_part[3 * BB * AA + b * AA + col];
#pragma unroll
            for (int i = 0; i < 8; i++)
                rowsum[i] += vj * tanhf(acc[i][j] + dpv);
        }
    }

#pragma unroll
    for (int off = 8; off > 0; off >>= 1)
#pragma unroll
        for (int i = 0; i < 8; i++)
            rowsum[i] += __shfl_down_sync(0xffffffffu, rowsum[i], off, 16);

    if (tx == 0) {
#pragma unroll
        for (int i = 0; i < 8; i++)
            g_energy_part[(long long)ntile * MROWS + bt0 + ty * 8 + i] = rowsum[i];
    }
    #undef TK
    #undef XS_STRIDE
    #undef WS_STRIDE
#endif
}

// ---------------------------------------------------------------------------
// sum 2 energy partials, mask, softmax -> att
// ---------------------------------------------------------------------------
__global__ __launch_bounds__(256) void softmax_kernel(
    const int* __restrict__ x_lens,
    float* __restrict__ att)
{
    __shared__ float red[32];
    const int b = blockIdx.x;
    const int tid = threadIdx.x;
    const int len = x_lens[b];
    float* e = att + b * TT;

    float vals[8];
    float mx = -INFINITY;
#pragma unroll
    for (int i = 0; i < 8; i++) {
        int t = i * 256 + tid;
        int idx = b * TT + t;
        float val = g_energy_part[idx] + g_energy_part[MROWS + idx];
        val = val * (t < len ? 1.0f : 0.0f);
        vals[i] = val;
        mx = fmaxf(mx, val);
    }
    for (int off = 16; off > 0; off >>= 1)
        mx = fmaxf(mx, __shfl_down_sync(0xffffffffu, mx, off));
    if ((tid & 31) == 0) red[tid >> 5] = mx;
    __syncthreads();
    if (tid < 32) {
        float m = (tid < 8) ? red[tid] : -INFINITY;
        for (int off = 4; off > 0; off >>= 1)
            m = fmaxf(m, __shfl_down_sync(0xffffffffu, m, off));
        if (tid == 0) red[0] = m;
    }
    __syncthreads();
    mx = red[0];

    float sum = 0.0f;
#pragma unroll
    for (int i = 0; i < 8; i++) {
        vals[i] = expf(vals[i] - mx);
        sum += vals[i];
    }
    for (int off = 16; off > 0; off >>= 1)
        sum += __shfl_down_sync(0xffffffffu, sum, off);
    __syncthreads();
    if ((tid & 31) == 0) red[tid >> 5] = sum;
    __syncthreads();
    if (tid < 32) {
        float s = (tid < 8) ? red[tid] : 0.0f;
        for (int off = 4; off > 0; off >>= 1)
            s += __shfl_down_sync(0xffffffffu, s, off);
        if (tid == 0) red[0] = s;
    }
    __syncthreads();
    float inv = 1.0f / red[0];

#pragma unroll
    for (int i = 0; i < 8; i++) {
        int t = i * 256 + tid;
        e[t] = vals[i] * inv;
    }
}

// ---------------------------------------------------------------------------
// context partials: 16 T-chunks of 128, float4 per thread, then reduce
// ---------------------------------------------------------------------------
__global__ __launch_bounds__(256) void context_part_kernel(
    const float* __restrict__ enc,
    const float* __restrict__ att)
{
    __shared__ float a_s[128];
    const int b = blockIdx.y;
    const int t0 = blockIdx.x * 128;
    if (threadIdx.x < 128) a_s[threadIdx.x] = att[b * TT + t0 + threadIdx.x];
    __syncthreads();
    const float4* __restrict__ base =
        reinterpret_cast<const float4*>(enc + ((long long)b * TT + t0) * EE)
        + threadIdx.x;
    float4 acc = make_float4(0.f, 0.f, 0.f, 0.f);
#pragma unroll 4
    for (int t = 0; t < 128; t++) {
        float4 x = base[(long long)t * 256];
        float a = a_s[t];
        acc.x += x.x * a; acc.y += x.y * a; acc.z += x.z * a; acc.w += x.w * a;
    }
    reinterpret_cast<float4*>(
        g_ctx_part + ((long long)blockIdx.x * BB + b) * EE)[threadIdx.x] = acc;
}

__global__ __launch_bounds__(256) void context_reduce_kernel(float* __restrict__ ctx)
{
    int i = blockIdx.x * 256 + threadIdx.x;
    float acc = 0.0f;
#pragma unroll
    for (int p = 0; p < 16; p++) acc += g_ctx_part[(long long)p * (BB * EE) + i];
    ctx[i] = acc;
}

// ---------------------------------------------------------------------------
extern "C" void kernel_launch(void* const* d_in, const int* in_sizes, int n_in,
                              void* d_out, int out_size)
{
    const float* enc_out = (const float*)d_in[0];   // [B,T,E]
    const int*   x_lens  = (const int*)  d_in[1];   // [B]
    const float* dec_out = (const float*)d_in[2];   // [B,1,D]
    const float* W_enc   = (const float*)d_in[4];   // [E,A]
    const float* b_enc   = (const float*)d_in[5];   // [A]
    const float* W_dec   = (const float*)d_in[6];   // [D,A]
    const float* v       = (const float*)d_in[7];   // [A]

    float* out = (float*)d_out;
    float* ctx = out;               // [B, E]
    float* att = out + BB * EE;     // [B, T]

    cudaFuncSetAttribute(energy_kernel,
                         cudaFuncAttributeMaxDynamicSharedMemorySize, SM_TOTAL);

    convert_w_kernel<<<dim3(32, 32), 1024>>>(W_enc);
    dec_proj_kernel<<<dim3(AA / 256, BB, 4), 256>>>(dec_out, W_dec, b_enc);
    energy_kernel<<<1024, 256, SM_TOTAL>>>(enc_out, W_enc, v);
    softmax_kernel<<<BB, 256>>>(x_lens, att);
    context_part_kernel<<<dim3(16, BB), 256>>>(enc_out, att);
    context_reduce_kernel<<<(BB * EE) / 256, 256>>>(ctx);
}